// round 14
// baseline (speedup 1.0000x reference)
#include <cuda_runtime.h>
#include <cuda_fp16.h>
#include <cstdint>

// EfficientAttention3D — fp16 mma.sync m16n8k16 (R12).
//   proj_kernel  : PERSISTENT single wave (148 CTAs, 6-7 tiles each). Wq/Wk staged
//                  once per CTA; x double-buffered across tiles; Wv restaged per
//                  tile (L2-hot) under the epilogues; K-side exp via ex2.approx.f16x2.
//   reduce_kernel: unchanged (34-CTA tile reduction).
//   finalize     : unchanged.
//   out_kernel   : unchanged from R11 (OT=8, double-buffered, streaming stores).

#define NB   2
#define CH   128
#define LEN  65536
#define TL   128
#define NT   (LEN/TL)
#define NCLS 4
#define OT   8
#define GTOT (NB*NT)     // 1024 tiles total
#define PCTA 148         // persistent proj CTAs

// proj smem byte offsets (total 231424 B)
#define B_WQ 0
#define B_WK 32768
#define B_WV 65536
#define B_X0 98304
#define B_X1 131072
#define B_ES 163840
#define B_QB 196608
#define B_RS 229376
#define SMEM_PROJ 231424
#define SMEM_OUT  98304

__device__ __align__(16) __half g_qs[(size_t)NB*NT*16384];   // per-tile rotated [l][ch]
__device__ float g_part[(size_t)NB*2176*NT];                 // [n][elem][tile]
__device__ float g_ctx[NB*2176];
__device__ float g_M[NB*CH*CH];

__device__ __forceinline__ uint32_t smem_u32(const void* p){
  uint32_t a; asm("{ .reg .u64 t; cvta.to.shared.u64 t, %1; cvt.u32.u64 %0, t; }":"=r"(a):"l"(p)); return a;
}
__device__ __forceinline__ void mma16(float d[4], const uint32_t a[4], uint32_t b0, uint32_t b1){
  asm volatile("mma.sync.aligned.m16n8k16.row.col.f32.f16.f16.f32 "
    "{%0,%1,%2,%3}, {%4,%5,%6,%7}, {%8,%9}, {%0,%1,%2,%3};"
    : "+f"(d[0]),"+f"(d[1]),"+f"(d[2]),"+f"(d[3])
    : "r"(a[0]),"r"(a[1]),"r"(a[2]),"r"(a[3]),"r"(b0),"r"(b1));
}
__device__ __forceinline__ void ldsm4(uint32_t* r, uint32_t a){
  asm volatile("ldmatrix.sync.aligned.m8n8.x4.shared.b16 {%0,%1,%2,%3}, [%4];"
    : "=r"(r[0]),"=r"(r[1]),"=r"(r[2]),"=r"(r[3]) : "r"(a));
}
__device__ __forceinline__ uint32_t h2ex2(uint32_t a){
  uint32_t r; asm("ex2.approx.f16x2 %0, %1;" : "=r"(r) : "r"(a)); return r;
}

// rotated-chunk layout: element (r,c) of a [R][128] fp16 tile lives at
//   r*256 + (((c>>3)+r)&15)*16 + (c&7)*2
__device__ __forceinline__ void stH2(__half* b, int r, int c, float v0, float v1){
  *(__half2*)((char*)b + r*256 + ((((c>>3)+r)&15)<<4) + (c&7)*2) = __floats2half2_rn(v0,v1);
}
__device__ __forceinline__ void stH2r(__half* b, int r, int c, uint32_t packed){
  *(uint32_t*)((char*)b + r*256 + ((((c>>3)+r)&15)<<4) + (c&7)*2) = packed;
}

__device__ __forceinline__ void stageXT(__half* xs, const float* __restrict__ src, int tid, size_t srcPitch){
  const int l = tid&127, cg = tid>>7;
#pragma unroll
  for (int pass=0; pass<4; pass++){
    const int c0 = pass*32 + cg*8;
    __half h[8];
#pragma unroll
    for (int i=0;i<8;i++) h[i] = __float2half(__ldg(src + (size_t)(c0+i)*srcPitch + l));
    *(uint4*)((char*)xs + l*256 + ((((c0>>3)+l)&15)<<4)) = *(uint4*)h;
  }
}
__device__ __forceinline__ void stageWH(__half* ws, const float* __restrict__ src, int tid, int srcPitch){
  const int o = tid>>4, ch = tid&15;
#pragma unroll
  for (int pass=0; pass<4; pass++){
    const int oo = pass*32 + o;
    const float* p = src + (size_t)oo*srcPitch + ch*8;
    float4 f0 = *(const float4*)p, f1 = *(const float4*)(p+4);
    __half h[8] = {__float2half(f0.x),__float2half(f0.y),__float2half(f0.z),__float2half(f0.w),
                   __float2half(f1.x),__float2half(f1.y),__float2half(f1.z),__float2half(f1.w)};
    *(uint4*)((char*)ws + oo*256 + (((ch+oo)&15)<<4)) = *(uint4*)h;
  }
}

// A: ws [128 m][128 k] fp16 rotated; B: xs [128 n][128 k] fp16 rotated. Warp tile 32x32.
__device__ __forceinline__ void gemm16(uint32_t wsb, uint32_t xsb, float acc[2][4][4],
                                       int wr, int wc, int lane)
{
#pragma unroll
  for (int m=0;m<2;m++)
#pragma unroll
    for (int n=0;n<4;n++)
#pragma unroll
      for (int j=0;j<4;j++) acc[m][n][j]=0.f;
  const int ar0 = wr*32 + (lane&15), ar1 = ar0 + 16;
  const int ach = lane>>4;
  const uint32_t a0b = wsb + ar0*256, a1b = wsb + ar1*256;
  const int br0 = wc*32 + (lane&7) + ((lane>>4)<<3), br1 = br0 + 16;
  const int bch = (lane>>3)&1;
  const uint32_t b0b = xsb + br0*256, b1b = xsb + br1*256;
#pragma unroll
  for (int k=0;k<8;k++){
    uint32_t a0[4],a1[4],b0[4],b1[4];
    ldsm4(a0, a0b + (((2*k+ach+ar0)&15)<<4));
    ldsm4(a1, a1b + (((2*k+ach+ar1)&15)<<4));
    ldsm4(b0, b0b + (((2*k+bch+br0)&15)<<4));
    ldsm4(b1, b1b + (((2*k+bch+br1)&15)<<4));
    mma16(acc[0][0], a0, b0[0], b0[1]); mma16(acc[1][0], a1, b0[0], b0[1]);
    mma16(acc[0][1], a0, b0[2], b0[3]); mma16(acc[1][1], a1, b0[2], b0[3]);
    mma16(acc[0][2], a0, b1[0], b1[1]); mma16(acc[1][2], a1, b1[0], b1[1]);
    mma16(acc[0][3], a0, b1[2], b1[3]); mma16(acc[1][3], a1, b1[2], b1[3]);
  }
}

extern "C" __global__ void __launch_bounds__(512,1)
proj_kernel(const float* __restrict__ x,
            const float* __restrict__ Wk, const float* __restrict__ bk,
            const float* __restrict__ Wq, const float* __restrict__ bq,
            const float* __restrict__ Wv, const float* __restrict__ bv)
{
  extern __shared__ char smb[];
  __half* wq = (__half*)(smb + B_WQ);
  __half* wk = (__half*)(smb + B_WK);
  __half* wv = (__half*)(smb + B_WV);   // Wv -> vs each tile
  __half* xb[2] = { (__half*)(smb + B_X0), (__half*)(smb + B_X1) };
  __half* es = (__half*)(smb + B_ES);
  __half* qb = (__half*)(smb + B_QB);
  float*  rs = (float*)(smb + B_RS);
  const int tid = threadIdx.x, wid = tid>>5, lane = tid&31;
  const int wr = wid&3, wc = wid>>2, lr = lane>>2, lc = lane&3;
  const uint32_t wqb = smem_u32(wq), wkb = smem_u32(wk), wvb = smem_u32(wv);
  const uint32_t xbb[2] = { smem_u32(xb[0]), smem_u32(xb[1]) };
  const float L2E = 1.4426950408889634f;

  // prologue: weights once, first x tile
  stageWH(wq, Wq, tid, CH);
  stageWH(wk, Wk, tid, CH);
  {
    const int g0 = blockIdx.x;
    stageXT(xb[0], x + (size_t)(g0>>9)*CH*LEN + (size_t)(g0&511)*TL, tid, LEN);
  }
  __syncthreads();

  int buf = 0;
  for (int g = blockIdx.x; g < GTOT; g += PCTA){
    const int n = g>>9, tile = g&511;
    const uint32_t xsb = xbb[buf];

    float accQ[2][4][4], accK[2][4][4];
    gemm16(wqb, xsb, accQ, wr, wc, lane);
    gemm16(wkb, xsb, accK, wr, wc, lane);

    // stage next x tile into the other buffer (no readers until next iter)
    const int gn = g + PCTA;
    if (gn < GTOT)
      stageXT(xb[buf^1], x + (size_t)(gn>>9)*CH*LEN + (size_t)(gn&511)*TL, tid, LEN);
    // restage Wv (L2-hot; latency hides under epilogues)
    stageWH(wv, Wv, tid, CH);

    // ---- Q epilogue: fp32 exp + 16-channel softmax -> qb ----
#pragma unroll
    for (int m=0;m<2;m++){
      const int rt = wr*32 + m*16 + lr, rb = rt + 8;
      const float bt = __ldg(bq + rt), bb = __ldg(bq + rb);
      float e[4][4], s0[4], s1[4];
#pragma unroll
      for (int nn=0;nn<4;nn++){
        e[nn][0]=__expf(accQ[m][nn][0]+bt); e[nn][1]=__expf(accQ[m][nn][1]+bt);
        e[nn][2]=__expf(accQ[m][nn][2]+bb); e[nn][3]=__expf(accQ[m][nn][3]+bb);
        s0[nn]=e[nn][0]+e[nn][2]; s1[nn]=e[nn][1]+e[nn][3];
      }
#pragma unroll
      for (int nn=0;nn<4;nn++){
        s0[nn] += __shfl_xor_sync(0xffffffffu, s0[nn], 4);
        s0[nn] += __shfl_xor_sync(0xffffffffu, s0[nn], 8);
        s0[nn] += __shfl_xor_sync(0xffffffffu, s0[nn], 16);
        s1[nn] += __shfl_xor_sync(0xffffffffu, s1[nn], 4);
        s1[nn] += __shfl_xor_sync(0xffffffffu, s1[nn], 8);
        s1[nn] += __shfl_xor_sync(0xffffffffu, s1[nn], 16);
        float i0 = __frcp_rn(s0[nn]), i1 = __frcp_rn(s1[nn]);
        int c = wc*32 + nn*8 + lc*2;
        *(__half*)((char*)qb + c*256     + ((((rt>>3)+c  )&15)<<4) + (rt&7)*2) = __float2half(e[nn][0]*i0);
        *(__half*)((char*)qb + (c+1)*256 + ((((rt>>3)+c+1)&15)<<4) + (rt&7)*2) = __float2half(e[nn][1]*i1);
        *(__half*)((char*)qb + c*256     + ((((rb>>3)+c  )&15)<<4) + (rb&7)*2) = __float2half(e[nn][2]*i0);
        *(__half*)((char*)qb + (c+1)*256 + ((((rb>>3)+c+1)&15)<<4) + (rb&7)*2) = __float2half(e[nn][3]*i1);
      }
    }
    // ---- K epilogue: ex2.approx.f16x2 -> es (+ fp32 rowsums) ----
#pragma unroll
    for (int m=0;m<2;m++){
      const int rt = wr*32 + m*16 + lr, rb = rt + 8;
      const float btL = __ldg(bk + rt)*L2E, bbL = __ldg(bk + rb)*L2E;
      float rowt=0.f, rowb=0.f;
#pragma unroll
      for (int nn=0;nn<4;nn++){
        float y0 = fmaf(accK[m][nn][0], L2E, btL);
        float y1 = fmaf(accK[m][nn][1], L2E, btL);
        float y2 = fmaf(accK[m][nn][2], L2E, bbL);
        float y3 = fmaf(accK[m][nn][3], L2E, bbL);
        __half2 p01 = __floats2half2_rn(y0,y1), p23 = __floats2half2_rn(y2,y3);
        uint32_t e01 = h2ex2(*(uint32_t*)&p01);
        uint32_t e23 = h2ex2(*(uint32_t*)&p23);
        int c = wc*32 + nn*8 + lc*2;
        stH2r(es, rt, c, e01);
        stH2r(es, rb, c, e23);
        float2 f0 = __half22float2(*(__half2*)&e01), f1 = __half22float2(*(__half2*)&e23);
        rowt += f0.x+f0.y; rowb += f1.x+f1.y;
      }
      rowt += __shfl_xor_sync(0xffffffffu, rowt, 1);
      rowt += __shfl_xor_sync(0xffffffffu, rowt, 2);
      rowb += __shfl_xor_sync(0xffffffffu, rowb, 1);
      rowb += __shfl_xor_sync(0xffffffffu, rowb, 2);
      if (lc == 0){ rs[rt*4+wc]=rowt; rs[rb*4+wc]=rowb; }
    }
    __syncthreads();   // qb/es/rs written, wv staged, xn staged

    // ---- V GEMM; qs copy overlaps ----
    float accV[2][4][4];
    gemm16(wvb, xsb, accV, wr, wc, lane);
    {
      uint4* dst = (uint4*)g_qs + (size_t)(n*NT + tile)*2048;
      const uint4* srcq = (const uint4*)qb;
#pragma unroll
      for (int j=0;j<4;j++) dst[tid + j*512] = srcq[tid + j*512];
    }
    __syncthreads();   // wv(Wv) reads + qb reads done
#pragma unroll
    for (int m=0;m<2;m++){
      const int rt = wr*32 + m*16 + lr, rb = rt + 8;
      const float bt = __ldg(bv + rt), bb = __ldg(bv + rb);
#pragma unroll
      for (int nn=0;nn<4;nn++){
        int c = wc*32 + nn*8 + lc*2;
        stH2(wv, rt, c, accV[m][nn][0]+bt, accV[m][nn][1]+bt);
        stH2(wv, rb, c, accV[m][nn][2]+bb, accV[m][nn][3]+bb);
      }
    }
    __syncthreads();   // vs ready

    // ---- context: ctx[h] = E_h @ V_h^T (split-K over warp pairs) ----
    float* pb = g_part + (size_t)n*2176*NT + tile;
    float* cbuf = (float*)qb;   // qb free after copy
    {
      const int h = wid>>1, kh = wid&1;
      const int ar = h*16 + (lane&15);
      const int ach = (lane>>4);
      const int brr = h*16 + (lane&7) + ((lane>>4)<<3);
      const int bch = (lane>>3)&1;
      const uint32_t ab = smem_u32(es) + ar*256;
      const uint32_t bbv = wvb + brr*256;
      float ca[2][4];
#pragma unroll
      for (int nt=0;nt<2;nt++)
#pragma unroll
        for (int j=0;j<4;j++) ca[nt][j]=0.f;
#pragma unroll
      for (int ks=0;ks<4;ks++){
        const int c2 = kh*8 + ks*2;
        uint32_t a[4], b[4];
        ldsm4(a, ab  + (((c2+ach+ar )&15)<<4));
        ldsm4(b, bbv + (((c2+bch+brr)&15)<<4));
        mma16(ca[0], a, b[0], b[1]);
        mma16(ca[1], a, b[2], b[3]);
      }
      if (kh == 1){
#pragma unroll
        for (int nt=0;nt<2;nt++){
          int v = nt*8 + lc*2;
          *(float2*)(cbuf + h*256 + lr*16     + v) = make_float2(ca[nt][0], ca[nt][1]);
          *(float2*)(cbuf + h*256 + (lr+8)*16 + v) = make_float2(ca[nt][2], ca[nt][3]);
        }
      }
      __syncthreads();
      if (kh == 0){
#pragma unroll
        for (int nt=0;nt<2;nt++){
          int v = nt*8 + lc*2;
          pb[(size_t)(h*256 + lr*16 + v    )*NT] = ca[nt][0] + cbuf[h*256 + lr*16 + v];
          pb[(size_t)(h*256 + lr*16 + v + 1)*NT] = ca[nt][1] + cbuf[h*256 + lr*16 + v + 1];
          pb[(size_t)(h*256 + (lr+8)*16 + v    )*NT] = ca[nt][2] + cbuf[h*256 + (lr+8)*16 + v];
          pb[(size_t)(h*256 + (lr+8)*16 + v + 1)*NT] = ca[nt][3] + cbuf[h*256 + (lr+8)*16 + v + 1];
        }
      }
    }
    if (tid < CH)
      pb[(size_t)(2048 + tid)*NT] = rs[tid*4] + rs[tid*4+1] + rs[tid*4+2] + rs[tid*4+3];
    __syncthreads();   // es/qb/rs/vs reads done before next-iter overwrite
    buf ^= 1;
  }
}

// ---------------- reduce: g_part [elem][NT] -> g_ctx [elem] ----------------
extern "C" __global__ void __launch_bounds__(512,1)
reduce_kernel()
{
  const int n = blockIdx.y;
  const int tid = threadIdx.x, wid = tid>>5, lane = tid&31;
  const int o0 = (blockIdx.x*16 + wid)*8;
#pragma unroll
  for (int j=0;j<8;j++){
    const int o = o0 + j;
    const float* p = g_part + ((size_t)n*2176 + o)*NT + lane*4;
    float s = 0.f;
#pragma unroll
    for (int i=0;i<4;i++){ float4 v = *(const float4*)(p + i*128); s += v.x+v.y+v.z+v.w; }
    s += __shfl_xor_sync(0xffffffffu, s, 16);
    s += __shfl_xor_sync(0xffffffffu, s, 8);
    s += __shfl_xor_sync(0xffffffffu, s, 4);
    s += __shfl_xor_sync(0xffffffffu, s, 2);
    s += __shfl_xor_sync(0xffffffffu, s, 1);
    if (lane == 0) g_ctx[n*2176 + o] = s;
  }
}

// ---------------- finalize ----------------
extern "C" __global__ void __launch_bounds__(512,1)
finalize_kernel(const float* __restrict__ CLS,
                const float* __restrict__ Wr,
                float* __restrict__ out)
{
  __shared__ float ctx[2048];
  __shared__ float Ssum[128];
  __shared__ float ecls[512];
  __shared__ float clsv[512];
  __shared__ float cn[2048];
  const int n = blockIdx.x;
  const int tid = threadIdx.x;

  for (int o=tid; o<2176; o+=512){
    float s = g_ctx[n*2176 + o];
    if (o < 2048) ctx[o] = s; else Ssum[o-2048] = s;
  }
  if (tid < 512){
    float v = CLS[(size_t)n*CH*NCLS + tid];
    clsv[tid]=v; ecls[tid]=__expf(v);
  }
  __syncthreads();
  if (tid < 128){
    float s = Ssum[tid];
#pragma unroll
    for (int j=0;j<NCLS;j++) s += ecls[tid*NCLS+j];
    Ssum[tid]=s;
  }
  __syncthreads();
  for (int idx=tid; idx<2048; idx+=512){
    int h=idx>>8, k=(idx>>4)&15, v=idx&15;
    float s=ctx[idx];
#pragma unroll
    for (int j=0;j<NCLS;j++) s += ecls[(h*16+k)*NCLS+j]*clsv[(h*16+v)*NCLS+j];
    cn[idx] = s / Ssum[h*16+k];
  }
  __syncthreads();
  if (tid < 256) out[(size_t)NB*CH*LEN + n*256 + tid] = cn[7*256 + tid];
  if (tid < 64){
    int v=tid>>2, j=tid&3;
    float se=0.f, a=0.f;
#pragma unroll
    for (int k=0;k<16;k++){
      float e = ecls[(112+k)*NCLS + j];
      se += e;
      a  += cn[7*256 + k*16 + v]*e;
    }
    out[(size_t)NB*CH*LEN + (size_t)NB*256 + n*64 + v*4 + j] = a/se;
  }
  for (int idx=tid; idx<CH*CH; idx+=512){
    int o=idx>>7, c=idx&127, h=c>>4, k=c&15;
    float m=0.f;
#pragma unroll
    for (int v=0;v<16;v++) m += Wr[o*CH + h*16+v]*cn[h*256 + k*16 + v];
    g_M[(size_t)n*CH*CH + idx] = m;
  }
}

// ---------------- out: attention = M @ qs + br, OT tiles, double-buffered ----------------
extern "C" __global__ void __launch_bounds__(512,1)
out_kernel(const float* __restrict__ br, float* __restrict__ out)
{
  extern __shared__ char smb[];
  __half* xsA[2] = { (__half*)smb, (__half*)(smb + 32768) };
  __half* ms = (__half*)(smb + 65536);
  const int tid = threadIdx.x, wid = tid>>5, lane = tid&31;
  const int wr = wid&3, wc = wid>>2, lr = lane>>2, lc = lane&3;
  const int n = blockIdx.y;
  const uint32_t msb = smem_u32(ms);
  const uint32_t xsb[2] = { smem_u32(xsA[0]), smem_u32(xsA[1]) };

  stageWH(ms, g_M + (size_t)n*CH*CH, tid, CH);

  const float bt0[2] = { __ldg(br + wr*32 + lr), __ldg(br + wr*32 + 16 + lr) };
  const float bb0[2] = { __ldg(br + wr*32 + 8 + lr), __ldg(br + wr*32 + 24 + lr) };

  const uint4* qbase = (const uint4*)g_qs + (size_t)(n*NT + blockIdx.x*OT)*2048;

  {
    uint4* dst = (uint4*)xsA[0];
#pragma unroll
    for (int j=0;j<4;j++) dst[tid + j*512] = qbase[tid + j*512];
  }
  __syncthreads();

  int buf = 0;
  for (int t=0; t<OT; t++){
    uint4 pf[4];
    if (t+1 < OT){
      const uint4* srcq = qbase + (size_t)(t+1)*2048;
#pragma unroll
      for (int j=0;j<4;j++) pf[j] = srcq[tid + j*512];
    }

    float acc[2][4][4];
    gemm16(msb, xsb[buf], acc, wr, wc, lane);

    float* og = out + (size_t)n*CH*LEN + (blockIdx.x*OT + t)*TL;
#pragma unroll
    for (int m=0;m<2;m++){
      const int rt = wr*32 + m*16 + lr, rb = rt + 8;
#pragma unroll
      for (int nn=0;nn<4;nn++){
        int c = wc*32 + nn*8 + lc*2;
        __stcs((float2*)(og + (size_t)rt*LEN + c), make_float2(acc[m][nn][0]+bt0[m], acc[m][nn][1]+bt0[m]));
        __stcs((float2*)(og + (size_t)rb*LEN + c), make_float2(acc[m][nn][2]+bb0[m], acc[m][nn][3]+bb0[m]));
      }
    }

    if (t+1 < OT){
      uint4* dst = (uint4*)xsA[buf^1];
#pragma unroll
      for (int j=0;j<4;j++) dst[tid + j*512] = pf[j];
      __syncthreads();
      buf ^= 1;
    }
  }
}

extern "C" void kernel_launch(void* const* d_in, const int* in_sizes, int n_in,
                              void* d_out, int out_size)
{
  const float* x  = (const float*)d_in[0];
  const float* CLS= (const float*)d_in[1];
  const float* Wk = (const float*)d_in[2];
  const float* bk = (const float*)d_in[3];
  const float* Wq = (const float*)d_in[4];
  const float* bq = (const float*)d_in[5];
  const float* Wv = (const float*)d_in[6];
  const float* bv = (const float*)d_in[7];
  const float* Wr = (const float*)d_in[8];
  const float* br = (const float*)d_in[9];
  float* out = (float*)d_out;

  cudaFuncSetAttribute(proj_kernel, cudaFuncAttributeMaxDynamicSharedMemorySize, SMEM_PROJ);
  cudaFuncSetAttribute(out_kernel,  cudaFuncAttributeMaxDynamicSharedMemorySize, SMEM_OUT);

  proj_kernel<<<PCTA, 512, SMEM_PROJ>>>(x, Wk, bk, Wq, bq, Wv, bv);
  dim3 gr(17, NB);
  reduce_kernel<<<gr, 512>>>();
  finalize_kernel<<<NB, 512>>>(CLS, Wr, out);
  dim3 go(NT/OT, NB);
  out_kernel<<<go, 512, SMEM_OUT>>>(br, out);
}

// round 16
// speedup vs baseline: 1.2823x; 1.2823x over previous
#include <cuda_runtime.h>
#include <cuda_fp16.h>
#include <cstdint>

// EfficientAttention3D — fp16 mma.sync m16n8k16 (R16 = R15 with corrected B-frag pairing).
//   proj_kernel  : 256 threads, 8 warps (warp tile 32x64), Q/K/V GEMMs sequential
//                  (one 64-reg acc live at a time) -> 2 CTAs/SM target. Buffers:
//                  xs(x->vs), wA(Wq->qh->Wv), wB(Wk->es). Context = warp per head.
//                  K-side exp via ex2.approx.f16x2.
//   reduce_kernel: 34-CTA tile reduction.
//   finalize     : tiny.
//   out_kernel   : OT=8, double-buffered, streaming stores (R11-validated).

#define NB   2
#define CH   128
#define LEN  65536
#define TL   128
#define NT   (LEN/TL)
#define NCLS 4
#define OT   8

// proj smem byte offsets (256-thread version)
#define B_XS 0          // 32KB x tile [l][ch] -> vs
#define B_WA 32768      // 32KB Wq -> qh -> Wv
#define B_WB 65536      // 32KB Wk -> es
#define B_RS 98304      // 1KB rowsum partials (256 floats)
#define SMEM_PROJ 99328
#define SMEM_OUT  98304

__device__ __align__(16) __half g_qs[(size_t)NB*NT*16384];   // per-tile rotated [l][ch]
__device__ float g_part[(size_t)NB*2176*NT];                 // [n][elem][tile]
__device__ float g_ctx[NB*2176];
__device__ float g_M[NB*CH*CH];

__device__ __forceinline__ uint32_t smem_u32(const void* p){
  uint32_t a; asm("{ .reg .u64 t; cvta.to.shared.u64 t, %1; cvt.u32.u64 %0, t; }":"=r"(a):"l"(p)); return a;
}
__device__ __forceinline__ void mma16(float d[4], const uint32_t a[4], uint32_t b0, uint32_t b1){
  asm volatile("mma.sync.aligned.m16n8k16.row.col.f32.f16.f16.f32 "
    "{%0,%1,%2,%3}, {%4,%5,%6,%7}, {%8,%9}, {%0,%1,%2,%3};"
    : "+f"(d[0]),"+f"(d[1]),"+f"(d[2]),"+f"(d[3])
    : "r"(a[0]),"r"(a[1]),"r"(a[2]),"r"(a[3]),"r"(b0),"r"(b1));
}
__device__ __forceinline__ void ldsm4(uint32_t* r, uint32_t a){
  asm volatile("ldmatrix.sync.aligned.m8n8.x4.shared.b16 {%0,%1,%2,%3}, [%4];"
    : "=r"(r[0]),"=r"(r[1]),"=r"(r[2]),"=r"(r[3]) : "r"(a));
}
__device__ __forceinline__ uint32_t h2ex2(uint32_t a){
  uint32_t r; asm("ex2.approx.f16x2 %0, %1;" : "=r"(r) : "r"(a)); return r;
}

// rotated-chunk layout: element (r,c) of a [R][128] fp16 tile lives at
//   r*256 + (((c>>3)+r)&15)*16 + (c&7)*2
__device__ __forceinline__ void stH2(__half* b, int r, int c, float v0, float v1){
  *(__half2*)((char*)b + r*256 + ((((c>>3)+r)&15)<<4) + (c&7)*2) = __floats2half2_rn(v0,v1);
}
__device__ __forceinline__ void stH2r(__half* b, int r, int c, uint32_t packed){
  *(uint32_t*)((char*)b + r*256 + ((((c>>3)+r)&15)<<4) + (c&7)*2) = packed;
}

// ---- 256-thread staging ----
__device__ __forceinline__ void stageXT256(__half* xs, const float* __restrict__ src, int tid, size_t srcPitch){
  const int l = tid&127, cg = tid>>7;   // cg in {0,1}
#pragma unroll
  for (int pass=0; pass<8; pass++){
    const int c0 = pass*16 + cg*8;
    __half h[8];
#pragma unroll
    for (int i=0;i<8;i++) h[i] = __float2half(__ldg(src + (size_t)(c0+i)*srcPitch + l));
    *(uint4*)((char*)xs + l*256 + ((((c0>>3)+l)&15)<<4)) = *(uint4*)h;
  }
}
__device__ __forceinline__ void stageWH256(__half* ws, const float* __restrict__ src, int tid, int srcPitch){
  const int o = tid>>4, ch = tid&15;    // o in 0..15
#pragma unroll
  for (int pass=0; pass<8; pass++){
    const int oo = pass*16 + o;
    const float* p = src + (size_t)oo*srcPitch + ch*8;
    float4 f0 = *(const float4*)p, f1 = *(const float4*)(p+4);
    __half h[8] = {__float2half(f0.x),__float2half(f0.y),__float2half(f0.z),__float2half(f0.w),
                   __float2half(f1.x),__float2half(f1.y),__float2half(f1.z),__float2half(f1.w)};
    *(uint4*)((char*)ws + oo*256 + (((ch+oo)&15)<<4)) = *(uint4*)h;
  }
}
// ---- 512-thread staging (out_kernel) ----
__device__ __forceinline__ void stageWH(__half* ws, const float* __restrict__ src, int tid, int srcPitch){
  const int o = tid>>4, ch = tid&15;
#pragma unroll
  for (int pass=0; pass<4; pass++){
    const int oo = pass*32 + o;
    const float* p = src + (size_t)oo*srcPitch + ch*8;
    float4 f0 = *(const float4*)p, f1 = *(const float4*)(p+4);
    __half h[8] = {__float2half(f0.x),__float2half(f0.y),__float2half(f0.z),__float2half(f0.w),
                   __float2half(f1.x),__float2half(f1.y),__float2half(f1.z),__float2half(f1.w)};
    *(uint4*)((char*)ws + oo*256 + (((ch+oo)&15)<<4)) = *(uint4*)h;
  }
}

// 512-thread gemm (out_kernel): warp tile 32x32, acc[2][4][4] — R11-validated pairing.
__device__ __forceinline__ void gemm16(uint32_t wsb, uint32_t xsb, float acc[2][4][4],
                                       int wr, int wc, int lane)
{
#pragma unroll
  for (int m=0;m<2;m++)
#pragma unroll
    for (int n=0;n<4;n++)
#pragma unroll
      for (int j=0;j<4;j++) acc[m][n][j]=0.f;
  const int ar0 = wr*32 + (lane&15), ar1 = ar0 + 16;
  const int ach = lane>>4;
  const uint32_t a0b = wsb + ar0*256, a1b = wsb + ar1*256;
  const int br0 = wc*32 + (lane&7) + ((lane>>4)<<3), br1 = br0 + 16;
  const int bch = (lane>>3)&1;
  const uint32_t b0b = xsb + br0*256, b1b = xsb + br1*256;
#pragma unroll
  for (int k=0;k<8;k++){
    uint32_t a0[4],a1[4],b0[4],b1[4];
    ldsm4(a0, a0b + (((2*k+ach+ar0)&15)<<4));
    ldsm4(a1, a1b + (((2*k+ach+ar1)&15)<<4));
    ldsm4(b0, b0b + (((2*k+bch+br0)&15)<<4));
    ldsm4(b1, b1b + (((2*k+bch+br1)&15)<<4));
    mma16(acc[0][0], a0, b0[0], b0[1]); mma16(acc[1][0], a1, b0[0], b0[1]);
    mma16(acc[0][1], a0, b0[2], b0[3]); mma16(acc[1][1], a1, b0[2], b0[3]);
    mma16(acc[0][2], a0, b1[0], b1[1]); mma16(acc[1][2], a1, b1[0], b1[1]);
    mma16(acc[0][3], a0, b1[2], b1[3]); mma16(acc[1][3], a1, b1[2], b1[3]);
  }
}

// 256-thread gemm (proj): warp tile 32x64, acc[2][8][4]; validated 16-row block
// pattern replicated over 4 n-blocks, with the CORRECT (b[0],b[1])/(b[2],b[3]) pairing.
__device__ __forceinline__ void gemm16w(uint32_t wsb, uint32_t xsb, float acc[2][8][4],
                                        int wr, int wc, int lane)
{
#pragma unroll
  for (int m=0;m<2;m++)
#pragma unroll
    for (int n=0;n<8;n++)
#pragma unroll
      for (int j=0;j<4;j++) acc[m][n][j]=0.f;
  const int ar0 = wr*32 + (lane&15), ar1 = ar0 + 16;
  const int ach = lane>>4;
  const uint32_t a0b = wsb + ar0*256, a1b = wsb + ar1*256;
  const int blane = (lane&7) + ((lane>>4)<<3);
  const int bch = (lane>>3)&1;
  int brr[4]; uint32_t bbs[4];
#pragma unroll
  for (int blk=0;blk<4;blk++){ brr[blk] = wc*64 + blk*16 + blane; bbs[blk] = xsb + (uint32_t)brr[blk]*256; }
#pragma unroll
  for (int k=0;k<8;k++){
    uint32_t a0[4],a1[4];
    ldsm4(a0, a0b + (((2*k+ach+ar0)&15)<<4));
    ldsm4(a1, a1b + (((2*k+ach+ar1)&15)<<4));
#pragma unroll
    for (int blk=0;blk<4;blk++){
      uint32_t b[4];
      ldsm4(b, bbs[blk] + (((2*k+bch+brr[blk])&15)<<4));
      mma16(acc[0][blk*2  ], a0, b[0], b[1]); mma16(acc[1][blk*2  ], a1, b[0], b[1]);
      mma16(acc[0][blk*2+1], a0, b[2], b[3]); mma16(acc[1][blk*2+1], a1, b[2], b[3]);
    }
  }
}

extern "C" __global__ void __launch_bounds__(256,2)
proj_kernel(const float* __restrict__ x,
            const float* __restrict__ Wk, const float* __restrict__ bk,
            const float* __restrict__ Wq, const float* __restrict__ bq,
            const float* __restrict__ Wv, const float* __restrict__ bv)
{
  extern __shared__ char smb[];
  __half* xs = (__half*)(smb + B_XS);   // x -> vs
  __half* wA = (__half*)(smb + B_WA);   // Wq -> qh -> Wv
  __half* wB = (__half*)(smb + B_WB);   // Wk -> es
  float*  rs = (float*)(smb + B_RS);
  const int tid = threadIdx.x, wid = tid>>5, lane = tid&31;
  const int wr = wid&3, wc = wid>>2, lr = lane>>2, lc = lane&3;
  const int n = blockIdx.y, tile = blockIdx.x;
  const uint32_t xsb = smem_u32(xs), wAb = smem_u32(wA), wBb = smem_u32(wB);
  const float L2E = 1.4426950408889634f;

  stageXT256(xs, x + (size_t)n*CH*LEN + (size_t)tile*TL, tid, LEN);
  stageWH256(wA, Wq, tid, CH);
  stageWH256(wB, Wk, tid, CH);
  __syncthreads();

  // ---- Q GEMM ----
  {
    float accQ[2][8][4];
    gemm16w(wAb, xsb, accQ, wr, wc, lane);
    __syncthreads();   // all warps done reading wA(Wq)

    // Q epilogue: fp32 exp + 16-channel softmax -> wA as [l][ch] fp16 rotated
#pragma unroll
    for (int m=0;m<2;m++){
      const int rt = wr*32 + m*16 + lr, rb = rt + 8;
      const float bt = __ldg(bq + rt), bb = __ldg(bq + rb);
      float e[8][4], s0[8], s1[8];
#pragma unroll
      for (int nn=0;nn<8;nn++){
        e[nn][0]=__expf(accQ[m][nn][0]+bt); e[nn][1]=__expf(accQ[m][nn][1]+bt);
        e[nn][2]=__expf(accQ[m][nn][2]+bb); e[nn][3]=__expf(accQ[m][nn][3]+bb);
        s0[nn]=e[nn][0]+e[nn][2]; s1[nn]=e[nn][1]+e[nn][3];
      }
#pragma unroll
      for (int nn=0;nn<8;nn++){
        s0[nn] += __shfl_xor_sync(0xffffffffu, s0[nn], 4);
        s0[nn] += __shfl_xor_sync(0xffffffffu, s0[nn], 8);
        s0[nn] += __shfl_xor_sync(0xffffffffu, s0[nn], 16);
        s1[nn] += __shfl_xor_sync(0xffffffffu, s1[nn], 4);
        s1[nn] += __shfl_xor_sync(0xffffffffu, s1[nn], 8);
        s1[nn] += __shfl_xor_sync(0xffffffffu, s1[nn], 16);
        float i0 = __frcp_rn(s0[nn]), i1 = __frcp_rn(s1[nn]);
        int c = wc*64 + nn*8 + lc*2;
        *(__half*)((char*)wA + c*256     + ((((rt>>3)+c  )&15)<<4) + (rt&7)*2) = __float2half(e[nn][0]*i0);
        *(__half*)((char*)wA + (c+1)*256 + ((((rt>>3)+c+1)&15)<<4) + (rt&7)*2) = __float2half(e[nn][1]*i1);
        *(__half*)((char*)wA + c*256     + ((((rb>>3)+c  )&15)<<4) + (rb&7)*2) = __float2half(e[nn][2]*i0);
        *(__half*)((char*)wA + (c+1)*256 + ((((rb>>3)+c+1)&15)<<4) + (rb&7)*2) = __float2half(e[nn][3]*i1);
      }
    }
  }

  // ---- K GEMM (reads wB, xs — independent of wA writes above) ----
  {
    float accK[2][8][4];
    gemm16w(wBb, xsb, accK, wr, wc, lane);
    __syncthreads();   // qh(wA) writes complete; all warps done reading wB(Wk)

    // copy qh -> g_qs (overlaps K epilogue in other warps' slack)
    {
      uint4* dst = (uint4*)g_qs + (size_t)(n*NT + tile)*2048;
      const uint4* srcq = (const uint4*)wA;
#pragma unroll
      for (int j=0;j<8;j++) dst[tid + j*256] = srcq[tid + j*256];
    }
    // K epilogue: ex2.approx.f16x2 -> wB = es (+ fp32 rowsums)
#pragma unroll
    for (int m=0;m<2;m++){
      const int rt = wr*32 + m*16 + lr, rb = rt + 8;
      const float btL = __ldg(bk + rt)*L2E, bbL = __ldg(bk + rb)*L2E;
      float rowt=0.f, rowb=0.f;
#pragma unroll
      for (int nn=0;nn<8;nn++){
        float y0 = fmaf(accK[m][nn][0], L2E, btL);
        float y1 = fmaf(accK[m][nn][1], L2E, btL);
        float y2 = fmaf(accK[m][nn][2], L2E, bbL);
        float y3 = fmaf(accK[m][nn][3], L2E, bbL);
        __half2 p01 = __floats2half2_rn(y0,y1), p23 = __floats2half2_rn(y2,y3);
        uint32_t e01 = h2ex2(*(uint32_t*)&p01);
        uint32_t e23 = h2ex2(*(uint32_t*)&p23);
        int c = wc*64 + nn*8 + lc*2;
        stH2r(wB, rt, c, e01);
        stH2r(wB, rb, c, e23);
        float2 f0 = __half22float2(*(__half2*)&e01), f1 = __half22float2(*(__half2*)&e23);
        rowt += f0.x+f0.y; rowb += f1.x+f1.y;
      }
      rowt += __shfl_xor_sync(0xffffffffu, rowt, 1);
      rowt += __shfl_xor_sync(0xffffffffu, rowt, 2);
      rowb += __shfl_xor_sync(0xffffffffu, rowb, 1);
      rowb += __shfl_xor_sync(0xffffffffu, rowb, 2);
      if (lc == 0){ rs[rt*2+wc]=rowt; rs[rb*2+wc]=rowb; }
    }
  }
  __syncthreads();     // qh copy reads done -> wA reusable
  stageWH256(wA, Wv, tid, CH);
  __syncthreads();

  // ---- V GEMM ----
  {
    float accV[2][8][4];
    gemm16w(wAb, xsb, accV, wr, wc, lane);
    __syncthreads();   // all warps done reading xs -> xs reusable as vs
#pragma unroll
    for (int m=0;m<2;m++){
      const int rt = wr*32 + m*16 + lr, rb = rt + 8;
      const float bt = __ldg(bv + rt), bb = __ldg(bv + rb);
#pragma unroll
      for (int nn=0;nn<8;nn++){
        int c = wc*64 + nn*8 + lc*2;
        stH2(xs, rt, c, accV[m][nn][0]+bt, accV[m][nn][1]+bt);
        stH2(xs, rb, c, accV[m][nn][2]+bb, accV[m][nn][3]+bb);
      }
    }
  }
  __syncthreads();     // vs ready

  // ---- context: ctx[h] = E_h @ V_h^T, full warp per head (h = wid), K=128 ----
  float* pb = g_part + (size_t)n*2176*NT + tile;
  {
    const int h = wid;
    const int ar = h*16 + (lane&15);
    const int ach = lane>>4;
    const int brv = h*16 + (lane&7) + ((lane>>4)<<3);
    const int bch = (lane>>3)&1;
    const uint32_t ab  = wBb + (uint32_t)ar*256;
    const uint32_t bbv = xsb + (uint32_t)brv*256;
    float ca[2][4];
#pragma unroll
    for (int nt=0;nt<2;nt++)
#pragma unroll
      for (int j=0;j<4;j++) ca[nt][j]=0.f;
#pragma unroll
    for (int k=0;k<8;k++){
      uint32_t a[4], b[4];
      ldsm4(a, ab  + (((2*k+ach+ar )&15)<<4));
      ldsm4(b, bbv + (((2*k+bch+brv)&15)<<4));
      mma16(ca[0], a, b[0], b[1]);
      mma16(ca[1], a, b[2], b[3]);
    }
#pragma unroll
    for (int nt=0;nt<2;nt++){
      int v = nt*8 + lc*2;
      pb[(size_t)(h*256 + lr*16 + v    )*NT] = ca[nt][0];
      pb[(size_t)(h*256 + lr*16 + v + 1)*NT] = ca[nt][1];
      pb[(size_t)(h*256 + (lr+8)*16 + v    )*NT] = ca[nt][2];
      pb[(size_t)(h*256 + (lr+8)*16 + v + 1)*NT] = ca[nt][3];
    }
  }
  if (tid < CH)
    pb[(size_t)(2048 + tid)*NT] = rs[tid*2] + rs[tid*2+1];
}

// ---------------- reduce: g_part [elem][NT] -> g_ctx [elem] ----------------
extern "C" __global__ void __launch_bounds__(512,1)
reduce_kernel()
{
  const int n = blockIdx.y;
  const int tid = threadIdx.x, wid = tid>>5, lane = tid&31;
  const int o0 = (blockIdx.x*16 + wid)*8;
#pragma unroll
  for (int j=0;j<8;j++){
    const int o = o0 + j;
    const float* p = g_part + ((size_t)n*2176 + o)*NT + lane*4;
    float s = 0.f;
#pragma unroll
    for (int i=0;i<4;i++){ float4 v = *(const float4*)(p + i*128); s += v.x+v.y+v.z+v.w; }
    s += __shfl_xor_sync(0xffffffffu, s, 16);
    s += __shfl_xor_sync(0xffffffffu, s, 8);
    s += __shfl_xor_sync(0xffffffffu, s, 4);
    s += __shfl_xor_sync(0xffffffffu, s, 2);
    s += __shfl_xor_sync(0xffffffffu, s, 1);
    if (lane == 0) g_ctx[n*2176 + o] = s;
  }
}

// ---------------- finalize ----------------
extern "C" __global__ void __launch_bounds__(512,1)
finalize_kernel(const float* __restrict__ CLS,
                const float* __restrict__ Wr,
                float* __restrict__ out)
{
  __shared__ float ctx[2048];
  __shared__ float Ssum[128];
  __shared__ float ecls[512];
  __shared__ float clsv[512];
  __shared__ float cn[2048];
  const int n = blockIdx.x;
  const int tid = threadIdx.x;

  for (int o=tid; o<2176; o+=512){
    float s = g_ctx[n*2176 + o];
    if (o < 2048) ctx[o] = s; else Ssum[o-2048] = s;
  }
  if (tid < 512){
    float v = CLS[(size_t)n*CH*NCLS + tid];
    clsv[tid]=v; ecls[tid]=__expf(v);
  }
  __syncthreads();
  if (tid < 128){
    float s = Ssum[tid];
#pragma unroll
    for (int j=0;j<NCLS;j++) s += ecls[tid*NCLS+j];
    Ssum[tid]=s;
  }
  __syncthreads();
  for (int idx=tid; idx<2048; idx+=512){
    int h=idx>>8, k=(idx>>4)&15, v=idx&15;
    float s=ctx[idx];
#pragma unroll
    for (int j=0;j<NCLS;j++) s += ecls[(h*16+k)*NCLS+j]*clsv[(h*16+v)*NCLS+j];
    cn[idx] = s / Ssum[h*16+k];
  }
  __syncthreads();
  if (tid < 256) out[(size_t)NB*CH*LEN + n*256 + tid] = cn[7*256 + tid];
  if (tid < 64){
    int v=tid>>2, j=tid&3;
    float se=0.f, a=0.f;
#pragma unroll
    for (int k=0;k<16;k++){
      float e = ecls[(112+k)*NCLS + j];
      se += e;
      a  += cn[7*256 + k*16 + v]*e;
    }
    out[(size_t)NB*CH*LEN + (size_t)NB*256 + n*64 + v*4 + j] = a/se;
  }
  for (int idx=tid; idx<CH*CH; idx+=512){
    int o=idx>>7, c=idx&127, h=c>>4, k=c&15;
    float m=0.f;
#pragma unroll
    for (int v=0;v<16;v++) m += Wr[o*CH + h*16+v]*cn[h*256 + k*16 + v];
    g_M[(size_t)n*CH*CH + idx] = m;
  }
}

// ---------------- out: attention = M @ qs + br, OT tiles, double-buffered ----------------
extern "C" __global__ void __launch_bounds__(512,1)
out_kernel(const float* __restrict__ br, float* __restrict__ out)
{
  extern __shared__ char smb[];
  __half* xsA[2] = { (__half*)smb, (__half*)(smb + 32768) };
  __half* ms = (__half*)(smb + 65536);
  const int tid = threadIdx.x, wid = tid>>5, lane = tid&31;
  const int wr = wid&3, wc = wid>>2, lr = lane>>2, lc = lane&3;
  const int n = blockIdx.y;
  const uint32_t msb = smem_u32(ms);
  const uint32_t xsb[2] = { smem_u32(xsA[0]), smem_u32(xsA[1]) };

  stageWH(ms, g_M + (size_t)n*CH*CH, tid, CH);

  const float bt0[2] = { __ldg(br + wr*32 + lr), __ldg(br + wr*32 + 16 + lr) };
  const float bb0[2] = { __ldg(br + wr*32 + 8 + lr), __ldg(br + wr*32 + 24 + lr) };

  const uint4* qbase = (const uint4*)g_qs + (size_t)(n*NT + blockIdx.x*OT)*2048;

  {
    uint4* dst = (uint4*)xsA[0];
#pragma unroll
    for (int j=0;j<4;j++) dst[tid + j*512] = qbase[tid + j*512];
  }
  __syncthreads();

  int buf = 0;
  for (int t=0; t<OT; t++){
    uint4 pf[4];
    if (t+1 < OT){
      const uint4* srcq = qbase + (size_t)(t+1)*2048;
#pragma unroll
      for (int j=0;j<4;j++) pf[j] = srcq[tid + j*512];
    }

    float acc[2][4][4];
    gemm16(msb, xsb[buf], acc, wr, wc, lane);

    float* og = out + (size_t)n*CH*LEN + (blockIdx.x*OT + t)*TL;
#pragma unroll
    for (int m=0;m<2;m++){
      const int rt = wr*32 + m*16 + lr, rb = rt + 8;
#pragma unroll
      for (int nn=0;nn<4;nn++){
        int c = wc*32 + nn*8 + lc*2;
        __stcs((float2*)(og + (size_t)rt*LEN + c), make_float2(acc[m][nn][0]+bt0[m], acc[m][nn][1]+bt0[m]));
        __stcs((float2*)(og + (size_t)rb*LEN + c), make_float2(acc[m][nn][2]+bb0[m], acc[m][nn][3]+bb0[m]));
      }
    }

    if (t+1 < OT){
      uint4* dst = (uint4*)xsA[buf^1];
#pragma unroll
      for (int j=0;j<4;j++) dst[tid + j*512] = pf[j];
      __syncthreads();
      buf ^= 1;
    }
  }
}

extern "C" void kernel_launch(void* const* d_in, const int* in_sizes, int n_in,
                              void* d_out, int out_size)
{
  const float* x  = (const float*)d_in[0];
  const float* CLS= (const float*)d_in[1];
  const float* Wk = (const float*)d_in[2];
  const float* bk = (const float*)d_in[3];
  const float* Wq = (const float*)d_in[4];
  const float* bq = (const float*)d_in[5];
  const float* Wv = (const float*)d_in[6];
  const float* bv = (const float*)d_in[7];
  const float* Wr = (const float*)d_in[8];
  const float* br = (const float*)d_in[9];
  float* out = (float*)d_out;

  cudaFuncSetAttribute(proj_kernel, cudaFuncAttributeMaxDynamicSharedMemorySize, SMEM_PROJ);
  cudaFuncSetAttribute(out_kernel,  cudaFuncAttributeMaxDynamicSharedMemorySize, SMEM_OUT);

  dim3 gp(NT, NB);
  proj_kernel<<<gp, 256, SMEM_PROJ>>>(x, Wk, bk, Wq, bq, Wv, bv);
  dim3 gr(17, NB);
  reduce_kernel<<<gr, 512>>>();
  finalize_kernel<<<NB, 512>>>(CLS, Wr, out);
  dim3 go(NT/OT, NB);
  out_kernel<<<go, 512, SMEM_OUT>>>(br, out);
}